// round 15
// baseline (speedup 1.0000x reference)
#include <cuda_runtime.h>
#include <cuda_bf16.h>
#include <cuda_fp16.h>
#include <cstdint>

#define BSZ 4
#define CIN_ 256
#define CQK_ 128
#define NPT 4096
#define KT 64            // keys per tile (attention)
#define NT 64            // tiles
#define QT 128           // queries per CTA

// scratch (device globals; no allocation allowed)
__device__ __half g_qh[BSZ * NPT * CQK_];          // [b][n][o] fp16
__device__ __half g_kh[BSZ * NPT * CQK_];          // [b][m][o] fp16
__device__ __nv_bfloat16 g_vh[BSZ * CIN_ * NPT];   // [b][c][m] bf16 channel-major
// projection inputs, bf16 hi/lo, transposed to [b][n][c]
__device__ __nv_bfloat16 g_xh[BSZ * NPT * CIN_];
__device__ __nv_bfloat16 g_xl[BSZ * NPT * CIN_];
__device__ __nv_bfloat16 g_gh[BSZ * NPT * CIN_];
__device__ __nv_bfloat16 g_gl[BSZ * NPT * CIN_];
// weights bf16 hi/lo, [o 0..511][c] (Q rows 0-127, K 128-255, V 256-511)
__device__ __nv_bfloat16 g_wh[512 * CIN_];
__device__ __nv_bfloat16 g_wl[512 * CIN_];

// ================= helpers =================
__device__ __forceinline__ uint32_t smem_u32(const void* p) {
    uint32_t a;
    asm("{ .reg .u64 t; cvta.to.shared.u64 t, %1; cvt.u32.u64 %0, t; }" : "=r"(a) : "l"(p));
    return a;
}
__device__ __forceinline__ void cp_async16(uint32_t dst, const void* src) {
    asm volatile("cp.async.cg.shared.global [%0], [%1], 16;" :: "r"(dst), "l"(src) : "memory");
}
#define CP_COMMIT() asm volatile("cp.async.commit_group;" ::: "memory")
#define CP_WAIT0()  asm volatile("cp.async.wait_group 0;" ::: "memory")
#define CP_WAIT1()  asm volatile("cp.async.wait_group 1;" ::: "memory")

__device__ __forceinline__ void ldsm4(uint32_t addr, uint32_t r[4]) {
    asm volatile("ldmatrix.sync.aligned.m8n8.x4.shared.b16 {%0,%1,%2,%3}, [%4];"
        : "=r"(r[0]), "=r"(r[1]), "=r"(r[2]), "=r"(r[3]) : "r"(addr));
}
__device__ __forceinline__ void mma_f16(float c[4], const uint32_t a[4],
                                        uint32_t b0, uint32_t b1) {
    asm("mma.sync.aligned.m16n8k16.row.col.f32.f16.f16.f32 "
        "{%0,%1,%2,%3}, {%4,%5,%6,%7}, {%8,%9}, {%0,%1,%2,%3};"
        : "+f"(c[0]), "+f"(c[1]), "+f"(c[2]), "+f"(c[3])
        : "r"(a[0]), "r"(a[1]), "r"(a[2]), "r"(a[3]), "r"(b0), "r"(b1));
}
__device__ __forceinline__ void mma_bf16(float c[4], const uint32_t a[4],
                                         uint32_t b0, uint32_t b1) {
    asm("mma.sync.aligned.m16n8k16.row.col.f32.bf16.bf16.f32 "
        "{%0,%1,%2,%3}, {%4,%5,%6,%7}, {%8,%9}, {%0,%1,%2,%3};"
        : "+f"(c[0]), "+f"(c[1]), "+f"(c[2]), "+f"(c[3])
        : "r"(a[0]), "r"(a[1]), "r"(a[2]), "r"(a[3]), "r"(b0), "r"(b1));
}

// 256B-row swizzle (Q, K in attention)
__device__ __forceinline__ uint32_t sw256(int r, int byte) {
    return (uint32_t)(r * 256 + (((byte >> 4) ^ (r & 7)) << 4) + (byte & 15));
}
// 128B-row swizzle (V, proj tiles)
__device__ __forceinline__ uint32_t sw128(int r, int byte) {
    return (uint32_t)(r * 128 + (((byte >> 4) ^ (r & 7)) << 4) + (byte & 15));
}

__device__ __forceinline__ uint32_t h2u(float a, float b) {
    __half2 h = __floats2half2_rn(a, b);
    return *(uint32_t*)&h;
}
__device__ __forceinline__ uint32_t b2u(float a, float b) {
    __nv_bfloat162 h = __floats2bfloat162_rn(a, b);
    return *(uint32_t*)&h;
}

extern __shared__ __align__(16) char smem[];

// ================= conversion kernels =================
__global__ __launch_bounds__(256)
void conv_w(const float* __restrict__ Wq, const float* __restrict__ Wk,
            const float* __restrict__ Wv)
{
    int idx = blockIdx.x * 256 + threadIdx.x;      // [0, 512*256)
    int o = idx >> 8, c = idx & 255;
    float v = (o < 128) ? Wq[o * 256 + c]
            : (o < 256) ? Wk[(o - 128) * 256 + c]
                        : Wv[(o - 256) * 256 + c];
    __nv_bfloat16 h = __float2bfloat16_rn(v);
    g_wh[idx] = h;
    g_wl[idx] = __float2bfloat16_rn(v - __bfloat162float(h));
}

__global__ __launch_bounds__(256)
void conv_xg(const float* __restrict__ x, const float* __restrict__ gg)
{
    __shared__ float s[32][33];
    const int tid = threadIdx.x;
    const int b = blockIdx.z & 3;
    const bool isx = blockIdx.z < 4;
    const float* src = (isx ? x : gg) + (size_t)b * CIN_ * NPT;
    __nv_bfloat16* dh = (isx ? g_xh : g_gh) + (size_t)b * NPT * CIN_;
    __nv_bfloat16* dl = (isx ? g_xl : g_gl) + (size_t)b * NPT * CIN_;
    const int n0 = blockIdx.x * 32, c0 = blockIdx.y * 32;
#pragma unroll
    for (int i = 0; i < 4; i++) {
        int idx = tid + i * 256;
        int c = idx >> 5, n = idx & 31;
        s[c][n] = src[(size_t)(c0 + c) * NPT + n0 + n];
    }
    __syncthreads();
#pragma unroll
    for (int i = 0; i < 2; i++) {
        int idx = tid + i * 256;
        int n = idx >> 4, cp = idx & 15;
        float v0 = s[2 * cp][n], v1 = s[2 * cp + 1][n];
        __nv_bfloat16 h0 = __float2bfloat16_rn(v0), h1 = __float2bfloat16_rn(v1);
        size_t o = (size_t)(n0 + n) * CIN_ + c0 + 2 * cp;
        *(uint32_t*)&dh[o] = (uint32_t)__bfloat16_as_ushort(h0) |
                             ((uint32_t)__bfloat16_as_ushort(h1) << 16);
        *(uint32_t*)&dl[o] = b2u(v0 - __bfloat162float(h0), v1 - __bfloat162float(h1));
    }
}

// ================= tensor-core projection GEMM =================
#define PSTAGE 49152u        // { Ah 16K | Al 16K | Bh 8K | Bl 8K }
#define PBIAS  98304u
#define PROJ_SMEM 98560

__device__ __forceinline__ void load_pstage(uint32_t sb, int stage, int ct, int tid,
    const __nv_bfloat16* ah, const __nv_bfloat16* al, int b, int n0, int o0)
{
    uint32_t stg = sb + (uint32_t)stage * PSTAGE;
#pragma unroll
    for (int i = 0; i < 12; i++) {
        int c = tid + i * 256;                       // 3072 chunks of 16B
        if (c < 2048) {                              // A hi/lo: 128 rows x 128B
            const __nv_bfloat16* s = (c < 1024) ? ah : al;
            int cc = c & 1023;
            int r = cc >> 3, ch = cc & 7;
            const __nv_bfloat16* src = s + (size_t)(b * NPT + n0 + r) * CIN_ + ct * 64 + ch * 8;
            cp_async16(stg + ((c < 1024) ? 0u : 16384u) + sw128(r, ch * 16), src);
        } else {                                     // B hi/lo: 64 rows x 128B
            const __nv_bfloat16* s = (c < 2560) ? g_wh : g_wl;
            int cc = c & 511;
            int r = cc >> 3, ch = cc & 7;
            const __nv_bfloat16* src = s + (size_t)(o0 + r) * CIN_ + ct * 64 + ch * 8;
            cp_async16(stg + ((c < 2560) ? 32768u : 40960u) + sw128(r, ch * 16), src);
        }
    }
}

__global__ __launch_bounds__(256)
void proj_mma(const float* __restrict__ bq, const float* __restrict__ bk,
              const float* __restrict__ bv)
{
    const uint32_t sb = smem_u32(smem);
    const int tid = threadIdx.x;
    const int lane = tid & 31, wid = tid >> 5;
    const int g = lane >> 2, tig = lane & 3;
    const int r0 = wid * 16;
    const int b  = blockIdx.z;
    const int n0 = blockIdx.x * 128;
    const int oy = blockIdx.y;
    const int o0 = oy * 64;
    const int dstT = (oy < 2) ? 0 : (oy < 4) ? 1 : 2;   // Q / K / V

    const __nv_bfloat16* ah = (dstT == 0) ? g_xh : g_gh;
    const __nv_bfloat16* al = (dstT == 0) ? g_xl : g_gl;
    const float* biasp = (dstT == 0) ? (bq + o0) : (dstT == 1) ? (bk + o0 - 128) : (bv + o0 - 256);

    float* sBias = (float*)(smem + PBIAS);
    if (tid < 64) sBias[tid] = biasp[tid];

    load_pstage(sb, 0, 0, tid, ah, al, b, n0, o0);
    CP_COMMIT();

    float accC[8][4];
#pragma unroll
    for (int j = 0; j < 8; j++)
#pragma unroll
        for (int q = 0; q < 4; q++) accC[j][q] = 0.0f;

    for (int ct = 0; ct < 4; ct++) {
        CP_WAIT0();
        __syncthreads();
        if (ct < 3) { load_pstage(sb, (ct + 1) & 1, ct + 1, tid, ah, al, b, n0, o0); CP_COMMIT(); }

        const uint32_t stg = sb + (uint32_t)(ct & 1) * PSTAGE;
#pragma unroll
        for (int kk = 0; kk < 4; kk++) {
            uint32_t Ah[4], Al[4];
            {
                int rr = r0 + (lane & 15);
                int byte = kk * 32 + ((lane >> 4) & 1) * 16;
                ldsm4(stg + sw128(rr, byte), Ah);
                ldsm4(stg + 16384u + sw128(rr, byte), Al);
            }
#pragma unroll
            for (int jb = 0; jb < 4; jb++) {
                int rr = jb * 16 + ((lane >> 4) << 3) + (lane & 7);
                int byte = kk * 32 + ((lane >> 3) & 1) * 16;
                uint32_t Bh[4], Bl[4];
                ldsm4(stg + 32768u + sw128(rr, byte), Bh);
                ldsm4(stg + 40960u + sw128(rr, byte), Bl);
                mma_bf16(accC[2*jb],   Ah, Bh[0], Bh[1]);
                mma_bf16(accC[2*jb+1], Ah, Bh[2], Bh[3]);
                mma_bf16(accC[2*jb],   Al, Bh[0], Bh[1]);
                mma_bf16(accC[2*jb+1], Al, Bh[2], Bh[3]);
                mma_bf16(accC[2*jb],   Ah, Bl[0], Bl[1]);
                mma_bf16(accC[2*jb+1], Ah, Bl[2], Bl[3]);
            }
        }
    }
    __syncthreads();

    if (dstT < 2) {      // Q / K: [b][n][o] fp16
        __half* dst = (dstT == 0) ? g_qh : g_kh;
        int og = (dstT == 0) ? o0 : (o0 - 128);
#pragma unroll
        for (int jb = 0; jb < 4; jb++)
#pragma unroll
            for (int hb = 0; hb < 2; hb++) {
                int ol = jb * 16 + hb * 8 + 2 * tig;
                float b0 = sBias[ol], b1 = sBias[ol + 1];
                float* a = accC[2 * jb + hb];
                size_t i0 = (size_t)(b * NPT + n0 + r0 + g) * CQK_ + og + ol;
                size_t i1 = i0 + (size_t)8 * CQK_;
                *(uint32_t*)&dst[i0] = h2u(a[0] + b0, a[1] + b1);
                *(uint32_t*)&dst[i1] = h2u(a[2] + b0, a[3] + b1);
            }
    } else {             // V: transpose to [b][c][m] bf16 via smem
        __nv_bfloat16* sT = (__nv_bfloat16*)smem;    // [64][130]
#pragma unroll
        for (int jb = 0; jb < 4; jb++)
#pragma unroll
            for (int hb = 0; hb < 2; hb++) {
                int ol = jb * 16 + hb * 8 + 2 * tig;
                float b0 = sBias[ol], b1 = sBias[ol + 1];
                float* a = accC[2 * jb + hb];
                sT[(ol    ) * 130 + r0 + g]     = __float2bfloat16_rn(a[0] + b0);
                sT[(ol + 1) * 130 + r0 + g]     = __float2bfloat16_rn(a[1] + b1);
                sT[(ol    ) * 130 + r0 + g + 8] = __float2bfloat16_rn(a[2] + b0);
                sT[(ol + 1) * 130 + r0 + g + 8] = __float2bfloat16_rn(a[3] + b1);
            }
        __syncthreads();
#pragma unroll
        for (int i = 0; i < 16; i++) {
            int w = tid + i * 256;
            int o = w >> 6, nn = (w & 63) * 2;
            uint32_t val = *(uint32_t*)&sT[o * 130 + nn];
            *(uint32_t*)&g_vh[(size_t)(b * CIN_ + (o0 - 256) + o) * NPT + n0 + nn] = val;
        }
    }
}

// ======= Fused flash attention: two-tile software pipeline (S(t+1) || PV(t)) =======
#define SM_QH   0u           // Q fp16: 128 rows x 256B = 32K
#define SM_ST0  32768u       // 3-stage ring: { Kh 16K | V 32K } x3
#define STAGESZ 49152u
#define SM_P    180224u      // P exchange: 2 parity buffers x 16 regions x 1KB
#define SM_MAX  212992u      // [128][2] f32
#define SM_L    214016u      // [128][2] f32
#define SMEM_TOTAL 215040

__device__ __forceinline__ void load_stage(uint32_t sb, int buf, int m0, int tid,
    const __half* kh, const __nv_bfloat16* vh)
{
    uint32_t stg = sb + SM_ST0 + (uint32_t)buf * STAGESZ;
#pragma unroll
    for (int i = 0; i < 6; i++) {
        int c = tid + i * 512;                       // 3072 chunks of 16B
        if (c < 1024) {                              // Kh: 64 rows x 256B
            int r = c >> 4, ch = c & 15;
            const __half* src = kh + (size_t)(m0 + r) * CQK_ + ch * 8;
            cp_async16(stg + sw256(r, ch * 16), src);
        } else {                                     // V: 256 ch x 128B
            int cc = c - 1024;
            int r = cc >> 3, ch = cc & 7;            // r = channel
            const __nv_bfloat16* src = vh + (size_t)r * NPT + m0 + ch * 8;
            cp_async16(stg + 16384u + sw128(r, ch * 16), src);
        }
    }
}

__global__ __launch_bounds__(512, 1)
void attn_tc(const float* __restrict__ gin, const float* __restrict__ gamma_p,
             float* __restrict__ out)
{
    const uint32_t sb = smem_u32(smem);
    const int tid  = threadIdx.x;
    const int lane = tid & 31, wid = tid >> 5;
    const int wq = wid & 7, wh = wid >> 3;
    const int g = lane >> 2, tig = lane & 3;
    const int r0 = 16 * wq;
    const int b  = blockIdx.y;
    const int n0 = blockIdx.x * QT;
    const int n0w = 32 * wh;

    const __half* qh = g_qh + (size_t)(b * NPT + n0) * CQK_;
    const __half* kh = g_kh + (size_t)b * NPT * CQK_;
    const __nv_bfloat16* vh = g_vh + (size_t)b * CIN_ * NPT;

    const uint32_t ownReg  = (uint32_t)((wq * 2 + wh) * 1024) + (uint32_t)(lane * 4);
    const uint32_t peerReg = (uint32_t)((wq * 2 + (1 - wh)) * 1024) + (uint32_t)(lane * 4);

    // prologue: group A = { Q, stage0 }, group B = { stage1 }
#pragma unroll
    for (int i = 0; i < 4; i++) {
        int c = tid + i * 512;                       // 2048 chunks
        int r = c >> 4, ch = c & 15;
        const __half* src = qh + (size_t)r * CQK_ + ch * 8;
        cp_async16(sb + SM_QH + sw256(r, ch * 16), src);
    }
    load_stage(sb, 0, 0, tid, kh, vh);
    CP_COMMIT();
    load_stage(sb, 1, KT, tid, kh, vh);
    CP_COMMIT();

    float accO[16][4];
#pragma unroll
    for (int j = 0; j < 16; j++)
#pragma unroll
        for (int q = 0; q < 4; q++) accO[j][q] = 0.0f;

    float lsum0 = 0.0f, lsum1 = 0.0f;
    float m0r = 0.0f, m1r = 0.0f;
    uint32_t aP[2][4];

    CP_WAIT1();                  // group A (Q + stage0) done
    __syncthreads();

    // ---- preamble: S(0), tile-0 max, softmax(0) -> aP, STS P[0], pair-bar ----
    {
        const uint32_t sKh = sb + SM_ST0;
        float accS[4][4];
#pragma unroll
        for (int j = 0; j < 4; j++)
#pragma unroll
            for (int q = 0; q < 4; q++) accS[j][q] = 0.0f;
#pragma unroll
        for (int kk = 0; kk < 8; kk++) {
            uint32_t Ah[4];
            {
                int rr = r0 + (lane & 15);
                int byte = kk * 32 + ((lane >> 4) & 1) * 16;
                ldsm4(sb + SM_QH + sw256(rr, byte), Ah);
            }
#pragma unroll
            for (int jp = 0; jp < 2; jp++) {
                int rr = n0w + 16 * jp + ((lane >> 4) << 3) + (lane & 7);
                int byte = kk * 32 + ((lane >> 3) & 1) * 16;
                uint32_t Bh[4];
                ldsm4(sKh + sw256(rr, byte), Bh);
                mma_f16(accS[2*jp],   Ah, Bh[0], Bh[1]);
                mma_f16(accS[2*jp+1], Ah, Bh[2], Bh[3]);
            }
        }
        // tile-0 row max (fixed reference for all tiles)
        {
            float mA = fmaxf(fmaxf(accS[0][0], accS[0][1]), fmaxf(accS[1][0], accS[1][1]));
            mA = fmaxf(mA, fmaxf(fmaxf(accS[2][0], accS[2][1]), fmaxf(accS[3][0], accS[3][1])));
            float mB = fmaxf(fmaxf(accS[0][2], accS[0][3]), fmaxf(accS[1][2], accS[1][3]));
            mB = fmaxf(mB, fmaxf(fmaxf(accS[2][2], accS[2][3]), fmaxf(accS[3][2], accS[3][3])));
            mA = fmaxf(mA, __shfl_xor_sync(0xffffffffu, mA, 1));
            mA = fmaxf(mA, __shfl_xor_sync(0xffffffffu, mA, 2));
            mB = fmaxf(mB, __shfl_xor_sync(0xffffffffu, mB, 1));
            mB = fmaxf(mB, __shfl_xor_sync(0xffffffffu, mB, 2));
            float* sM = (float*)(smem + SM_MAX);
            if (tig == 0) {
                sM[(r0 + g) * 2 + wh]     = mA;
                sM[(r0 + g + 8) * 2 + wh] = mB;
            }
            __syncthreads();
            m0r = fmaxf(sM[(r0 + g) * 2],     sM[(r0 + g) * 2 + 1]);
            m1r = fmaxf(sM[(r0 + g + 8) * 2], sM[(r0 + g + 8) * 2 + 1]);
        }
        // softmax(0)
#pragma unroll
        for (int j = 0; j < 4; j++) {
            float e0 = __expf(accS[j][0] - m0r);
            float e1 = __expf(accS[j][1] - m0r);
            float e2 = __expf(accS[j][2] - m1r);
            float e3 = __expf(accS[j][3] - m1r);
            __nv_bfloat162 p01 = __floats2bfloat162_rn(e0, e1);
            __nv_bfloat162 p23 = __floats2bfloat162_rn(e2, e3);
            lsum0 += __bfloat162float(p01.x) + __bfloat162float(p01.y);
            lsum1 += __bfloat162float(p23.x) + __bfloat162float(p23.y);
            aP[j >> 1][((j & 1) << 1)]     = *(uint32_t*)&p01;
            aP[j >> 1][((j & 1) << 1) | 1] = *(uint32_t*)&p23;
        }
#pragma unroll
        for (int i = 0; i < 8; i++)
            *(uint32_t*)(smem + SM_P + ownReg + (uint32_t)(i * 128)) = aP[i >> 2][i & 3];
        asm volatile("bar.sync %0, %1;" :: "r"(1 + wq), "r"(64) : "memory");
    }

    // ---- pipelined main loop: iter t does PV(t) interleaved with S(t+1) ----
#pragma unroll 1
    for (int t = 0; t < NT - 1; t++) {
        CP_WAIT0();              // stage(t+1) resident
        __syncthreads();
        if (t + 2 < NT) { load_stage(sb, (t + 2) % 3, (t + 2) * KT, tid, kh, vh); CP_COMMIT(); }

        const uint32_t sV   = sb + SM_ST0 + (uint32_t)(t % 3) * STAGESZ + 16384u;
        const uint32_t sKh  = sb + SM_ST0 + (uint32_t)((t + 1) % 3) * STAGESZ;
        const uint32_t pPar = (uint32_t)(SM_P + (uint32_t)(t & 1) * 16384u) + peerReg;

        float accS[4][4];
#pragma unroll
        for (int j = 0; j < 4; j++)
#pragma unroll
            for (int q = 0; q < 4; q++) accS[j][q] = 0.0f;
        uint32_t Alive[4];

#pragma unroll
        for (int kk = 0; kk < 8; kk++) {
            // --- S(t+1) slice: 3 ldsm + 4 mma ---
            {
                uint32_t Ah[4];
                int rr = r0 + (lane & 15);
                int byte = kk * 32 + ((lane >> 4) & 1) * 16;
                ldsm4(sb + SM_QH + sw256(rr, byte), Ah);
#pragma unroll
                for (int jp = 0; jp < 2; jp++) {
                    int rr2 = n0w + 16 * jp + ((lane >> 4) << 3) + (lane & 7);
                    int byteB = kk * 32 + ((lane >> 3) & 1) * 16;
                    uint32_t Bh[4];
                    ldsm4(sKh + sw256(rr2, byteB), Bh);
                    mma_f16(accS[2*jp],   Ah, Bh[0], Bh[1]);
                    mma_f16(accS[2*jp+1], Ah, Bh[2], Bh[3]);
                }
            }
            // --- PV(t): 4 units (ldsm + 2 mma each) ---
#pragma unroll
            for (int s = 0; s < 4; s++) {
                const int u = kk * 4 + s;
                const int cc = u >> 3;               // 0,1: own aP; 2,3: partner
                const int jp = u & 7;
                if (cc >= 2 && jp == 0) {
#pragma unroll
                    for (int ai = 0; ai < 4; ai++)
                        Alive[ai] = *(const uint32_t*)(smem + pPar +
                            (uint32_t)(((cc - 2) * 4 + ai) * 128));
                }
                const uint32_t* Af = (cc == 0) ? aP[0] : (cc == 1) ? aP[1] : Alive;
                const int kkey = (cc < 2) ? (2 * wh + cc) : (2 * (1 - wh) + (cc - 2));
                int rr = 128 * wh + 16 * jp + ((lane >> 4) << 3) + (lane & 7);
                int byte = kkey * 32 + ((lane >> 3) & 1) * 16;
                uint32_t Bv[4];
                ldsm4(sV + sw128(rr, byte), Bv);
                mma_bf16(accO[2*jp],   Af, Bv[0], Bv[1]);
                mma_bf16(accO[2*jp+1], Af, Bv[2], Bv[3]);
            }
        }

        // --- softmax(t+1) -> aP; STS into parity buffer; pair-bar ---
#pragma unroll
        for (int j = 0; j < 4; j++) {
            float e0 = __expf(accS[j][0] - m0r);
            float e1 = __expf(accS[j][1] - m0r);
            float e2 = __expf(accS[j][2] - m1r);
            float e3 = __expf(accS[j][3] - m1r);
            __nv_bfloat162 p01 = __floats2bfloat162_rn(e0, e1);
            __nv_bfloat162 p23 = __floats2bfloat162_rn(e2, e3);
            lsum0 += __bfloat162float(p01.x) + __bfloat162float(p01.y);
            lsum1 += __bfloat162float(p23.x) + __bfloat162float(p23.y);
            aP[j >> 1][((j & 1) << 1)]     = *(uint32_t*)&p01;
            aP[j >> 1][((j & 1) << 1) | 1] = *(uint32_t*)&p23;
        }
        const uint32_t pOwnW = (uint32_t)(SM_P + (uint32_t)((t + 1) & 1) * 16384u) + ownReg;
#pragma unroll
        for (int i = 0; i < 8; i++)
            *(uint32_t*)(smem + pOwnW + (uint32_t)(i * 128)) = aP[i >> 2][i & 3];
        asm volatile("bar.sync %0, %1;" :: "r"(1 + wq), "r"(64) : "memory");
    }

    // ---- final PV(NT-1) ----
    {
        const int t = NT - 1;
        const uint32_t sV   = sb + SM_ST0 + (uint32_t)(t % 3) * STAGESZ + 16384u;
        const uint32_t pPar = (uint32_t)(SM_P + (uint32_t)(t & 1) * 16384u) + peerReg;
        uint32_t Alive[4];
#pragma unroll
        for (int u = 0; u < 32; u++) {
            const int cc = u >> 3;
            const int jp = u & 7;
            if (cc >= 2 && jp == 0) {
#pragma unroll
                for (int ai = 0; ai < 4; ai++)
                    Alive[ai] = *(const uint32_t*)(smem + pPar +
                        (uint32_t)(((cc - 2) * 4 + ai) * 128));
            }
            const uint32_t* Af = (cc == 0) ? aP[0] : (cc == 1) ? aP[1] : Alive;
            const int kkey = (cc < 2) ? (2 * wh + cc) : (2 * (1 - wh) + (cc - 2));
            int rr = 128 * wh + 16 * jp + ((lane >> 4) << 3) + (lane & 7);
            int byte = kkey * 32 + ((lane >> 3) & 1) * 16;
            uint32_t Bv[4];
            ldsm4(sV + sw128(rr, byte), Bv);
            mma_bf16(accO[2*jp],   Af, Bv[0], Bv[1]);
            mma_bf16(accO[2*jp+1], Af, Bv[2], Bv[3]);
        }
    }

    // ---- l reduction ----
    lsum0 += __shfl_xor_sync(0xffffffffu, lsum0, 1);
    lsum0 += __shfl_xor_sync(0xffffffffu, lsum0, 2);
    lsum1 += __shfl_xor_sync(0xffffffffu, lsum1, 1);
    lsum1 += __shfl_xor_sync(0xffffffffu, lsum1, 2);
    float* sL = (float*)(smem + SM_L);
    if (tig == 0) {
        sL[(r0 + g) * 2 + wh]     = lsum0;
        sL[(r0 + g + 8) * 2 + wh] = lsum1;
    }
    __syncthreads();
    const float rl0 = 1.0f / (sL[(r0 + g) * 2]     + sL[(r0 + g) * 2 + 1]);
    const float rl1 = 1.0f / (sL[(r0 + g + 8) * 2] + sL[(r0 + g + 8) * 2 + 1]);
    const float gam = gamma_p[0];

    // ---- epilogue: smem transpose, coalesced  out = gamma*O/l + g ----
    float* sT = (float*)(smem + SM_ST0);         // [64 ch][128 q] pad-132
#pragma unroll 1
    for (int blk = 0; blk < 4; blk++) {
        if (wh == (blk >> 1)) {
#pragma unroll
            for (int jj = 0; jj < 8; jj++) {
                int j  = 8 * (blk & 1) + jj;
                int cl = 8 * jj + 2 * tig;
                sT[(cl    ) * 132 + r0 + g]     = gam * accO[j][0] * rl0;
                sT[(cl + 1) * 132 + r0 + g]     = gam * accO[j][1] * rl0;
                sT[(cl    ) * 132 + r0 + g + 8] = gam * accO[j][2] * rl1;
                sT[(cl + 1) * 132 + r0 + g + 8] = gam * accO[j][3] * rl1;
            }
        }
        __syncthreads();
#pragma unroll
        for (int it = 0; it < 16; it++) {
            int idx = tid + it * 512;
            int q = idx & 127, cl = idx >> 7;
            size_t gi = (size_t)(b * CIN_ + 64 * blk + cl) * NPT + n0 + q;
            out[gi] = sT[cl * 132 + q] + gin[gi];
        }
        __syncthreads();
    }
}

// ================= launch =================
extern "C" void kernel_launch(void* const* d_in, const int* in_sizes, int n_in,
                              void* d_out, int out_size)
{
    const float* x     = (const float*)d_in[0];
    const float* g     = (const float*)d_in[1];
    const float* Wq    = (const float*)d_in[2];
    const float* bq    = (const float*)d_in[3];
    const float* Wk    = (const float*)d_in[4];
    const float* bk    = (const float*)d_in[5];
    const float* Wv    = (const float*)d_in[6];
    const float* bv    = (const float*)d_in[7];
    const float* gamma = (const float*)d_in[8];
    float* out = (float*)d_out;
    (void)in_sizes; (void)n_in; (void)out_size;

    cudaFuncSetAttribute(attn_tc, cudaFuncAttributeMaxDynamicSharedMemorySize, SMEM_TOTAL);
    cudaFuncSetAttribute(proj_mma, cudaFuncAttributeMaxDynamicSharedMemorySize, PROJ_SMEM);

    conv_w <<<512, 256>>>(Wq, Wk, Wv);
    conv_xg<<<dim3(NPT / 32, CIN_ / 32, 8), 256>>>(x, g);
    proj_mma<<<dim3(NPT / 128, 8, BSZ), 256, PROJ_SMEM>>>(bq, bk, bv);
    attn_tc<<<dim3(NPT / QT, BSZ), 512, SMEM_TOTAL>>>(g, gamma, out);
}

// round 16
// speedup vs baseline: 1.0786x; 1.0786x over previous
#include <cuda_runtime.h>
#include <cuda_bf16.h>
#include <cuda_fp16.h>
#include <cstdint>

#define BSZ 4
#define CIN_ 256
#define CQK_ 128
#define NPT 4096
#define KT 64            // keys per tile (attention)
#define NT 64            // tiles
#define QT 128           // queries per CTA

// scratch (device globals; no allocation allowed)
__device__ __half g_qh[BSZ * NPT * CQK_];          // [b][n][o] fp16
__device__ __half g_kh[BSZ * NPT * CQK_];          // [b][m][o] fp16
__device__ __nv_bfloat16 g_vh[BSZ * CIN_ * NPT];   // [b][c][m] bf16 channel-major
// projection inputs, bf16 hi/lo, transposed to [b][n][c]
__device__ __nv_bfloat16 g_xh[BSZ * NPT * CIN_];
__device__ __nv_bfloat16 g_xl[BSZ * NPT * CIN_];
__device__ __nv_bfloat16 g_gh[BSZ * NPT * CIN_];
__device__ __nv_bfloat16 g_gl[BSZ * NPT * CIN_];
// weights bf16 hi/lo, [o 0..511][c] (Q rows 0-127, K 128-255, V 256-511)
__device__ __nv_bfloat16 g_wh[512 * CIN_];
__device__ __nv_bfloat16 g_wl[512 * CIN_];

// ================= helpers =================
__device__ __forceinline__ uint32_t smem_u32(const void* p) {
    uint32_t a;
    asm("{ .reg .u64 t; cvta.to.shared.u64 t, %1; cvt.u32.u64 %0, t; }" : "=r"(a) : "l"(p));
    return a;
}
__device__ __forceinline__ void cp_async16(uint32_t dst, const void* src) {
    asm volatile("cp.async.cg.shared.global [%0], [%1], 16;" :: "r"(dst), "l"(src) : "memory");
}
#define CP_COMMIT() asm volatile("cp.async.commit_group;" ::: "memory")
#define CP_WAIT0()  asm volatile("cp.async.wait_group 0;" ::: "memory")

__device__ __forceinline__ void ldsm4(uint32_t addr, uint32_t r[4]) {
    asm volatile("ldmatrix.sync.aligned.m8n8.x4.shared.b16 {%0,%1,%2,%3}, [%4];"
        : "=r"(r[0]), "=r"(r[1]), "=r"(r[2]), "=r"(r[3]) : "r"(addr));
}
__device__ __forceinline__ void mma_f16(float c[4], const uint32_t a[4],
                                        uint32_t b0, uint32_t b1) {
    asm("mma.sync.aligned.m16n8k16.row.col.f32.f16.f16.f32 "
        "{%0,%1,%2,%3}, {%4,%5,%6,%7}, {%8,%9}, {%0,%1,%2,%3};"
        : "+f"(c[0]), "+f"(c[1]), "+f"(c[2]), "+f"(c[3])
        : "r"(a[0]), "r"(a[1]), "r"(a[2]), "r"(a[3]), "r"(b0), "r"(b1));
}
__device__ __forceinline__ void mma_bf16(float c[4], const uint32_t a[4],
                                         uint32_t b0, uint32_t b1) {
    asm("mma.sync.aligned.m16n8k16.row.col.f32.bf16.bf16.f32 "
        "{%0,%1,%2,%3}, {%4,%5,%6,%7}, {%8,%9}, {%0,%1,%2,%3};"
        : "+f"(c[0]), "+f"(c[1]), "+f"(c[2]), "+f"(c[3])
        : "r"(a[0]), "r"(a[1]), "r"(a[2]), "r"(a[3]), "r"(b0), "r"(b1));
}

// 256B-row swizzle (Q, K in attention)
__device__ __forceinline__ uint32_t sw256(int r, int byte) {
    return (uint32_t)(r * 256 + (((byte >> 4) ^ (r & 7)) << 4) + (byte & 15));
}
// 128B-row swizzle (V, proj tiles)
__device__ __forceinline__ uint32_t sw128(int r, int byte) {
    return (uint32_t)(r * 128 + (((byte >> 4) ^ (r & 7)) << 4) + (byte & 15));
}

__device__ __forceinline__ uint32_t h2u(float a, float b) {
    __half2 h = __floats2half2_rn(a, b);
    return *(uint32_t*)&h;
}
__device__ __forceinline__ uint32_t b2u(float a, float b) {
    __nv_bfloat162 h = __floats2bfloat162_rn(a, b);
    return *(uint32_t*)&h;
}

extern __shared__ __align__(16) char smem[];

// ================= conversion kernels =================
__global__ __launch_bounds__(256)
void conv_w(const float* __restrict__ Wq, const float* __restrict__ Wk,
            const float* __restrict__ Wv)
{
    int idx = blockIdx.x * 256 + threadIdx.x;      // [0, 512*256)
    int o = idx >> 8, c = idx & 255;
    float v = (o < 128) ? Wq[o * 256 + c]
            : (o < 256) ? Wk[(o - 128) * 256 + c]
                        : Wv[(o - 256) * 256 + c];
    __nv_bfloat16 h = __float2bfloat16_rn(v);
    g_wh[idx] = h;
    g_wl[idx] = __float2bfloat16_rn(v - __bfloat162float(h));
}

__global__ __launch_bounds__(256)
void conv_xg(const float* __restrict__ x, const float* __restrict__ gg)
{
    __shared__ float s[32][33];
    const int tid = threadIdx.x;
    const int b = blockIdx.z & 3;
    const bool isx = blockIdx.z < 4;
    const float* src = (isx ? x : gg) + (size_t)b * CIN_ * NPT;
    __nv_bfloat16* dh = (isx ? g_xh : g_gh) + (size_t)b * NPT * CIN_;
    __nv_bfloat16* dl = (isx ? g_xl : g_gl) + (size_t)b * NPT * CIN_;
    const int n0 = blockIdx.x * 32, c0 = blockIdx.y * 32;
#pragma unroll
    for (int i = 0; i < 4; i++) {
        int idx = tid + i * 256;
        int c = idx >> 5, n = idx & 31;
        s[c][n] = src[(size_t)(c0 + c) * NPT + n0 + n];
    }
    __syncthreads();
#pragma unroll
    for (int i = 0; i < 2; i++) {
        int idx = tid + i * 256;
        int n = idx >> 4, cp = idx & 15;
        float v0 = s[2 * cp][n], v1 = s[2 * cp + 1][n];
        __nv_bfloat16 h0 = __float2bfloat16_rn(v0), h1 = __float2bfloat16_rn(v1);
        size_t o = (size_t)(n0 + n) * CIN_ + c0 + 2 * cp;
        *(uint32_t*)&dh[o] = (uint32_t)__bfloat16_as_ushort(h0) |
                             ((uint32_t)__bfloat16_as_ushort(h1) << 16);
        *(uint32_t*)&dl[o] = b2u(v0 - __bfloat162float(h0), v1 - __bfloat162float(h1));
    }
}

// ================= tensor-core projection GEMM =================
// Q/K: 3-pass bf16 split (fp32-accurate). V: 1-pass bf16 (output is bf16 anyway;
// error ~1.6e-3 rel, same order as V storage rounding already in budget).
#define PSTAGE 49152u        // { Ah 16K | Al 16K | Bh 8K | Bl 8K }
#define PBIAS  98304u
#define PROJ_SMEM 98560

__device__ __forceinline__ void load_pstage(uint32_t sb, int stage, int ct, int tid,
    const __nv_bfloat16* ah, const __nv_bfloat16* al, int b, int n0, int o0, bool full)
{
    uint32_t stg = sb + (uint32_t)stage * PSTAGE;
#pragma unroll
    for (int i = 0; i < 12; i++) {
        int c = tid + i * 256;                       // 3072 chunks of 16B
        if (c < 2048) {                              // A hi/lo: 128 rows x 128B
            if (c >= 1024 && !full) continue;        // skip A-lo for V
            const __nv_bfloat16* s = (c < 1024) ? ah : al;
            int cc = c & 1023;
            int r = cc >> 3, ch = cc & 7;
            const __nv_bfloat16* src = s + (size_t)(b * NPT + n0 + r) * CIN_ + ct * 64 + ch * 8;
            cp_async16(stg + ((c < 1024) ? 0u : 16384u) + sw128(r, ch * 16), src);
        } else {                                     // B hi/lo: 64 rows x 128B
            if (c >= 2560 && !full) continue;        // skip B-lo for V
            const __nv_bfloat16* s = (c < 2560) ? g_wh : g_wl;
            int cc = c & 511;
            int r = cc >> 3, ch = cc & 7;
            const __nv_bfloat16* src = s + (size_t)(o0 + r) * CIN_ + ct * 64 + ch * 8;
            cp_async16(stg + ((c < 2560) ? 32768u : 40960u) + sw128(r, ch * 16), src);
        }
    }
}

__global__ __launch_bounds__(256)
void proj_mma(const float* __restrict__ bq, const float* __restrict__ bk,
              const float* __restrict__ bv)
{
    const uint32_t sb = smem_u32(smem);
    const int tid = threadIdx.x;
    const int lane = tid & 31, wid = tid >> 5;
    const int g = lane >> 2, tig = lane & 3;
    const int r0 = wid * 16;
    const int b  = blockIdx.z;
    const int n0 = blockIdx.x * 128;
    const int oy = blockIdx.y;
    const int o0 = oy * 64;
    const int dstT = (oy < 2) ? 0 : (oy < 4) ? 1 : 2;   // Q / K / V
    const bool full = (dstT < 2);                        // V = 1-pass

    const __nv_bfloat16* ah = (dstT == 0) ? g_xh : g_gh;
    const __nv_bfloat16* al = (dstT == 0) ? g_xl : g_gl;
    const float* biasp = (dstT == 0) ? (bq + o0) : (dstT == 1) ? (bk + o0 - 128) : (bv + o0 - 256);

    float* sBias = (float*)(smem + PBIAS);
    if (tid < 64) sBias[tid] = biasp[tid];

    load_pstage(sb, 0, 0, tid, ah, al, b, n0, o0, full);
    CP_COMMIT();

    float accC[8][4];
#pragma unroll
    for (int j = 0; j < 8; j++)
#pragma unroll
        for (int q = 0; q < 4; q++) accC[j][q] = 0.0f;

    for (int ct = 0; ct < 4; ct++) {
        CP_WAIT0();
        __syncthreads();
        if (ct < 3) { load_pstage(sb, (ct + 1) & 1, ct + 1, tid, ah, al, b, n0, o0, full); CP_COMMIT(); }

        const uint32_t stg = sb + (uint32_t)(ct & 1) * PSTAGE;
#pragma unroll
        for (int kk = 0; kk < 4; kk++) {
            uint32_t Ah[4], Al[4];
            {
                int rr = r0 + (lane & 15);
                int byte = kk * 32 + ((lane >> 4) & 1) * 16;
                ldsm4(stg + sw128(rr, byte), Ah);
                if (full) ldsm4(stg + 16384u + sw128(rr, byte), Al);
            }
#pragma unroll
            for (int jb = 0; jb < 4; jb++) {
                int rr = jb * 16 + ((lane >> 4) << 3) + (lane & 7);
                int byte = kk * 32 + ((lane >> 3) & 1) * 16;
                uint32_t Bh[4];
                ldsm4(stg + 32768u + sw128(rr, byte), Bh);
                mma_bf16(accC[2*jb],   Ah, Bh[0], Bh[1]);
                mma_bf16(accC[2*jb+1], Ah, Bh[2], Bh[3]);
                if (full) {
                    uint32_t Bl[4];
                    ldsm4(stg + 40960u + sw128(rr, byte), Bl);
                    mma_bf16(accC[2*jb],   Al, Bh[0], Bh[1]);
                    mma_bf16(accC[2*jb+1], Al, Bh[2], Bh[3]);
                    mma_bf16(accC[2*jb],   Ah, Bl[0], Bl[1]);
                    mma_bf16(accC[2*jb+1], Ah, Bl[2], Bl[3]);
                }
            }
        }
    }
    __syncthreads();

    if (dstT < 2) {      // Q / K: [b][n][o] fp16
        __half* dst = (dstT == 0) ? g_qh : g_kh;
        int og = (dstT == 0) ? o0 : (o0 - 128);
#pragma unroll
        for (int jb = 0; jb < 4; jb++)
#pragma unroll
            for (int hb = 0; hb < 2; hb++) {
                int ol = jb * 16 + hb * 8 + 2 * tig;
                float b0 = sBias[ol], b1 = sBias[ol + 1];
                float* a = accC[2 * jb + hb];
                size_t i0 = (size_t)(b * NPT + n0 + r0 + g) * CQK_ + og + ol;
                size_t i1 = i0 + (size_t)8 * CQK_;
                *(uint32_t*)&dst[i0] = h2u(a[0] + b0, a[1] + b1);
                *(uint32_t*)&dst[i1] = h2u(a[2] + b0, a[3] + b1);
            }
    } else {             // V: transpose to [b][c][m] bf16 via smem
        __nv_bfloat16* sT = (__nv_bfloat16*)smem;    // [64][130]
#pragma unroll
        for (int jb = 0; jb < 4; jb++)
#pragma unroll
            for (int hb = 0; hb < 2; hb++) {
                int ol = jb * 16 + hb * 8 + 2 * tig;
                float b0 = sBias[ol], b1 = sBias[ol + 1];
                float* a = accC[2 * jb + hb];
                sT[(ol    ) * 130 + r0 + g]     = __float2bfloat16_rn(a[0] + b0);
                sT[(ol + 1) * 130 + r0 + g]     = __float2bfloat16_rn(a[1] + b1);
                sT[(ol    ) * 130 + r0 + g + 8] = __float2bfloat16_rn(a[2] + b0);
                sT[(ol + 1) * 130 + r0 + g + 8] = __float2bfloat16_rn(a[3] + b1);
            }
        __syncthreads();
#pragma unroll
        for (int i = 0; i < 16; i++) {
            int w = tid + i * 256;
            int o = w >> 6, nn = (w & 63) * 2;
            uint32_t val = *(uint32_t*)&sT[o * 130 + nn];
            *(uint32_t*)&g_vh[(size_t)(b * CIN_ + (o0 - 256) + o) * NPT + n0 + nn] = val;
        }
    }
}

// ================= Fused mma.sync flash attention (1-pass fp16 S / bf16 PV) =================
#define SM_QH   0u           // Q fp16: 128 rows x 256B = 32K
#define SM_ST0  32768u       // stage: { Kh 16K | V 32K } = 48K, x2
#define STAGESZ 49152u
#define SM_P    131072u      // per-warp P fragment regions: 16 x 1KB
#define SM_MAX  147456u      // [128][2] f32
#define SM_L    148480u      // [128][2] f32
#define SMEM_TOTAL 149504

__device__ __forceinline__ void load_stage(uint32_t sb, int stage, int m0, int tid,
    const __half* kh, const __nv_bfloat16* vh)
{
    uint32_t stg = sb + SM_ST0 + (uint32_t)stage * STAGESZ;
#pragma unroll
    for (int i = 0; i < 6; i++) {
        int c = tid + i * 512;                       // 3072 chunks of 16B
        if (c < 1024) {                              // Kh: 64 rows x 256B
            int r = c >> 4, ch = c & 15;
            const __half* src = kh + (size_t)(m0 + r) * CQK_ + ch * 8;
            cp_async16(stg + sw256(r, ch * 16), src);
        } else {                                     // V: 256 ch x 128B
            int cc = c - 1024;
            int r = cc >> 3, ch = cc & 7;            // r = channel
            const __nv_bfloat16* src = vh + (size_t)r * NPT + m0 + ch * 8;
            cp_async16(stg + 16384u + sw128(r, ch * 16), src);
        }
    }
}

__global__ __launch_bounds__(512, 1)
void attn_tc(const float* __restrict__ gin, const float* __restrict__ gamma_p,
             float* __restrict__ out)
{
    const uint32_t sb = smem_u32(smem);
    const int tid  = threadIdx.x;
    const int lane = tid & 31, wid = tid >> 5;
    const int wq = wid & 7, wh = wid >> 3;
    const int g = lane >> 2, tig = lane & 3;
    const int r0 = 16 * wq;
    const int b  = blockIdx.y;
    const int n0 = blockIdx.x * QT;

    const __half* qh = g_qh + (size_t)(b * NPT + n0) * CQK_;
    const __half* kh = g_kh + (size_t)b * NPT * CQK_;
    const __nv_bfloat16* vh = g_vh + (size_t)b * CIN_ * NPT;

    const uint32_t pOwn  = sb + SM_P + (uint32_t)((wq * 2 + wh) * 1024) + (uint32_t)(lane * 4);
    const uint32_t pPeer = sb + SM_P + (uint32_t)((wq * 2 + (1 - wh)) * 1024) + (uint32_t)(lane * 4);

    // prologue: Q + stage0
#pragma unroll
    for (int i = 0; i < 4; i++) {
        int c = tid + i * 512;                       // 2048 chunks
        int r = c >> 4, ch = c & 15;
        const __half* src = qh + (size_t)r * CQK_ + ch * 8;
        cp_async16(sb + SM_QH + sw256(r, ch * 16), src);
    }
    load_stage(sb, 0, 0, tid, kh, vh);
    CP_COMMIT();

    float accO[16][4];
#pragma unroll
    for (int j = 0; j < 16; j++)
#pragma unroll
        for (int q = 0; q < 4; q++) accO[j][q] = 0.0f;

    float lsum0 = 0.0f, lsum1 = 0.0f;
    float m0r = 0.0f, m1r = 0.0f;
    const int n0w = 32 * wh;

    for (int t = 0; t < NT; t++) {
        CP_WAIT0();
        __syncthreads();
        if (t + 1 < NT) { load_stage(sb, (t + 1) & 1, (t + 1) * KT, tid, kh, vh); CP_COMMIT(); }

        const uint32_t stg = sb + SM_ST0 + (uint32_t)(t & 1) * STAGESZ;
        const uint32_t sKh = stg, sV = stg + 16384u;

        // ---- S = Q·K  (16 rows x 32 keys per warp, fp16 1-pass) ----
        float accS[4][4];
#pragma unroll
        for (int j = 0; j < 4; j++)
#pragma unroll
            for (int q = 0; q < 4; q++) accS[j][q] = 0.0f;

#pragma unroll
        for (int kk = 0; kk < 8; kk++) {
            uint32_t Ah[4];
            {
                int rr = r0 + (lane & 15);
                int byte = kk * 32 + ((lane >> 4) & 1) * 16;
                ldsm4(sb + SM_QH + sw256(rr, byte), Ah);
            }
#pragma unroll
            for (int jp = 0; jp < 2; jp++) {
                int rr = n0w + 16 * jp + ((lane >> 4) << 3) + (lane & 7);
                int byte = kk * 32 + ((lane >> 3) & 1) * 16;
                uint32_t Bh[4];
                ldsm4(sKh + sw256(rr, byte), Bh);
                mma_f16(accS[2*jp],   Ah, Bh[0], Bh[1]);
                mma_f16(accS[2*jp+1], Ah, Bh[2], Bh[3]);
            }
        }

        // ---- fixed row max from tile 0 ----
        if (t == 0) {
            float mA = fmaxf(fmaxf(accS[0][0], accS[0][1]), fmaxf(accS[1][0], accS[1][1]));
            mA = fmaxf(mA, fmaxf(fmaxf(accS[2][0], accS[2][1]), fmaxf(accS[3][0], accS[3][1])));
            float mB = fmaxf(fmaxf(accS[0][2], accS[0][3]), fmaxf(accS[1][2], accS[1][3]));
            mB = fmaxf(mB, fmaxf(fmaxf(accS[2][2], accS[2][3]), fmaxf(accS[3][2], accS[3][3])));
            mA = fmaxf(mA, __shfl_xor_sync(0xffffffffu, mA, 1));
            mA = fmaxf(mA, __shfl_xor_sync(0xffffffffu, mA, 2));
            mB = fmaxf(mB, __shfl_xor_sync(0xffffffffu, mB, 1));
            mB = fmaxf(mB, __shfl_xor_sync(0xffffffffu, mB, 2));
            float* sM = (float*)(smem + SM_MAX);
            if (tig == 0) {
                sM[(r0 + g) * 2 + wh]     = mA;
                sM[(r0 + g + 8) * 2 + wh] = mB;
            }
            __syncthreads();
            m0r = fmaxf(sM[(r0 + g) * 2],     sM[(r0 + g) * 2 + 1]);
            m1r = fmaxf(sM[(r0 + g + 8) * 2], sM[(r0 + g + 8) * 2 + 1]);
        }

        // ---- softmax: accS -> bf16 A-fragments in registers; l from rounded P ----
        uint32_t aP[2][4];
#pragma unroll
        for (int j = 0; j < 4; j++) {
            float e0 = __expf(accS[j][0] - m0r);
            float e1 = __expf(accS[j][1] - m0r);
            float e2 = __expf(accS[j][2] - m1r);
            float e3 = __expf(accS[j][3] - m1r);
            __nv_bfloat162 p01 = __floats2bfloat162_rn(e0, e1);
            __nv_bfloat162 p23 = __floats2bfloat162_rn(e2, e3);
            lsum0 += __bfloat162float(p01.x) + __bfloat162float(p01.y);
            lsum1 += __bfloat162float(p23.x) + __bfloat162float(p23.y);
            aP[j >> 1][((j & 1) << 1)]     = *(uint32_t*)&p01;
            aP[j >> 1][((j & 1) << 1) | 1] = *(uint32_t*)&p23;
        }

#pragma unroll
        for (int i = 0; i < 8; i++)
            *(uint32_t*)(smem + (pOwn - sb) + (uint32_t)(i * 128)) = aP[i >> 2][i & 3];

        // ---- PV own key-chunks first ----
#pragma unroll
        for (int cc = 0; cc < 2; cc++) {
            const int kk = 2 * wh + cc;
#pragma unroll
            for (int jp = 0; jp < 8; jp++) {
                int rr = 128 * wh + 16 * jp + ((lane >> 4) << 3) + (lane & 7);
                int byte = kk * 32 + ((lane >> 3) & 1) * 16;
                uint32_t Bv[4];
                ldsm4(sV + sw128(rr, byte), Bv);
                mma_bf16(accO[2*jp],   aP[cc], Bv[0], Bv[1]);
                mma_bf16(accO[2*jp+1], aP[cc], Bv[2], Bv[3]);
            }
        }

        asm volatile("bar.sync %0, %1;" :: "r"(1 + wq), "r"(64) : "memory");

        uint32_t aQ[2][4];
#pragma unroll
        for (int i = 0; i < 8; i++)
            aQ[i >> 2][i & 3] = *(const uint32_t*)(smem + (pPeer - sb) + (uint32_t)(i * 128));

        // ---- PV partner key-chunks ----
#pragma unroll
        for (int cc = 0; cc < 2; cc++) {
            const int kk = 2 * (1 - wh) + cc;
#pragma unroll
            for (int jp = 0; jp < 8; jp++) {
                int rr = 128 * wh + 16 * jp + ((lane >> 4) << 3) + (lane & 7);
                int byte = kk * 32 + ((lane >> 3) & 1) * 16;
                uint32_t Bv[4];
                ldsm4(sV + sw128(rr, byte), Bv);
                mma_bf16(accO[2*jp],   aQ[cc], Bv[0], Bv[1]);
                mma_bf16(accO[2*jp+1], aQ[cc], Bv[2], Bv[3]);
            }
        }
    }

    // ---- l reduction ----
    lsum0 += __shfl_xor_sync(0xffffffffu, lsum0, 1);
    lsum0 += __shfl_xor_sync(0xffffffffu, lsum0, 2);
    lsum1 += __shfl_xor_sync(0xffffffffu, lsum1, 1);
    lsum1 += __shfl_xor_sync(0xffffffffu, lsum1, 2);
    float* sL = (float*)(smem + SM_L);
    if (tig == 0) {
        sL[(r0 + g) * 2 + wh]     = lsum0;
        sL[(r0 + g + 8) * 2 + wh] = lsum1;
    }
    __syncthreads();
    const float rl0 = 1.0f / (sL[(r0 + g) * 2]     + sL[(r0 + g) * 2 + 1]);
    const float rl1 = 1.0f / (sL[(r0 + g + 8) * 2] + sL[(r0 + g + 8) * 2 + 1]);
    const float gam = gamma_p[0];

    // ---- epilogue: smem transpose, coalesced  out = gamma*O/l + g ----
    float* sT = (float*)(smem + SM_ST0);         // [64 ch][128 q] pad-132
#pragma unroll 1
    for (int blk = 0; blk < 4; blk++) {
        if (wh == (blk >> 1)) {
#pragma unroll
            for (int jj = 0; jj < 8; jj++) {
                int j  = 8 * (blk & 1) + jj;
                int cl = 8 * jj + 2 * tig;
                sT[(cl    ) * 132 + r0 + g]     = gam * accO[j][0] * rl0;
                sT[(cl + 1) * 132 + r0 + g]     = gam * accO[j][1] * rl0;
                sT[(cl    ) * 132 + r0 + g + 8] = gam * accO[j][2] * rl1;
                sT[(cl + 1) * 132 + r0 + g + 8] = gam * accO[j][3] * rl1;
            }
        }
        __syncthreads();
#pragma unroll
        for (int it = 0; it < 16; it++) {
            int idx = tid + it * 512;
            int q = idx & 127, cl = idx >> 7;
            size_t gi = (size_t)(b * CIN_ + 64 * blk + cl) * NPT + n0 + q;
            out[gi] = sT[cl * 132 + q] + gin[gi];
        }
        __syncthreads();
    }
}

// ================= launch =================
extern "C" void kernel_launch(void* const* d_in, const int* in_sizes, int n_in,
                              void* d_out, int out_size)
{
    const float* x     = (const float*)d_in[0];
    const float* g     = (const float*)d_in[1];
    const float* Wq    = (const float*)d_in[2];
    const float* bq    = (const float*)d_in[3];
    const float* Wk    = (const float*)d_in[4];
    const float* bk    = (const float*)d_in[5];
    const float* Wv    = (const float*)d_in[6];
    const float* bv    = (const float*)d_in[7];
    const float* gamma = (const float*)d_in[8];
    float* out = (float*)d_out;
    (void)in_sizes; (void)n_in; (void)out_size;

    cudaFuncSetAttribute(attn_tc, cudaFuncAttributeMaxDynamicSharedMemorySize, SMEM_TOTAL);
    cudaFuncSetAttribute(proj_mma, cudaFuncAttributeMaxDynamicSharedMemorySize, PROJ_SMEM);

    conv_w <<<512, 256>>>(Wq, Wk, Wv);
    conv_xg<<<dim3(NPT / 32, CIN_ / 32, 8), 256>>>(x, g);
    proj_mma<<<dim3(NPT / 128, 8, BSZ), 256, PROJ_SMEM>>>(bq, bk, bv);
    attn_tc<<<dim3(NPT / QT, BSZ), 512, SMEM_TOTAL>>>(g, gamma, out);
}